// round 4
// baseline (speedup 1.0000x reference)
#include <cuda_runtime.h>

#define BATCH  4
#define NPTS   8192
#define TOTAL  (BATCH * NPTS)
#define NB     1024
#define XMIN   (-5.0f)
#define XSPAN  10.0f
#define BH     (XSPAN / (float)NB)        // bucket width ~0.00977
#define INVH   ((float)NB / XSPAN)

// Scratch (__device__ globals — no allocation allowed):
__device__ float4 g_sorted[2][TOTAL];     // points sorted by x-bucket, per (array, batch)
__device__ int    g_hist[2][BATCH][NB];
__device__ int    g_off [2][BATCH][NB + 1];
__device__ int    g_cur [2][BATCH][NB];
__device__ float  g_min [2][TOTAL];

__device__ __forceinline__ int bucket_of(float x) {
    int b = (int)floorf((x - XMIN) * INVH);
    return min(max(b, 0), NB - 1);
}

__global__ void zero_kernel() {
    int i = blockIdx.x * blockDim.x + threadIdx.x;
    if (i < 2 * BATCH * NB) ((int*)g_hist)[i] = 0;
}

__global__ void hist_kernel(const float* __restrict__ p1,
                            const float* __restrict__ p2) {
    int i = blockIdx.x * blockDim.x + threadIdx.x;
    if (i >= TOTAL) return;
    int b = i / NPTS;
    atomicAdd(&g_hist[0][b][bucket_of(p1[3 * i])], 1);
    atomicAdd(&g_hist[1][b][bucket_of(p2[3 * i])], 1);
}

// One block per (array, batch): exclusive scan of the 1024-bucket histogram.
__global__ __launch_bounds__(NB) void prefix_kernel() {
    __shared__ int s[NB];
    int a = blockIdx.x >> 2, b = blockIdx.x & 3;
    int t = threadIdx.x;
    int cnt = g_hist[a][b][t];
    s[t] = cnt;
    __syncthreads();
    #pragma unroll
    for (int o = 1; o < NB; o <<= 1) {
        int x = (t >= o) ? s[t - o] : 0;
        __syncthreads();
        s[t] += x;
        __syncthreads();
    }
    int excl = s[t] - cnt;
    g_off[a][b][t] = excl;
    g_cur[a][b][t] = excl;
    if (t == NB - 1) g_off[a][b][NB] = s[t];   // == NPTS
}

__global__ void scatter_kernel(const float* __restrict__ p1,
                               const float* __restrict__ p2) {
    int i = blockIdx.x * blockDim.x + threadIdx.x;
    if (i >= TOTAL) return;
    int b = i / NPTS;
    {
        float x = p1[3 * i], y = p1[3 * i + 1], z = p1[3 * i + 2];
        int pos = atomicAdd(&g_cur[0][b][bucket_of(x)], 1);
        g_sorted[0][b * NPTS + pos] = make_float4(x, y, z, 0.0f);
    }
    {
        float x = p2[3 * i], y = p2[3 * i + 1], z = p2[3 * i + 2];
        int pos = atomicAdd(&g_cur[1][b][bucket_of(x)], 1);
        g_sorted[1][b * NPTS + pos] = make_float4(x, y, z, 0.0f);
    }
}

// One thread per query. Scan candidate buckets outward from the query's
// bucket; stop a side when (x-gap to that bucket's near edge)^2 >= best.
// Exact: the x-gap is a valid lower bound on dist^2 (conservative under clamp).
__global__ __launch_bounds__(256) void nn_kernel() {
    int g = blockIdx.x * blockDim.x + threadIdx.x;
    if (g >= 2 * TOTAL) return;
    int dir = g / TOTAL;
    int rem = g - dir * TOTAL;
    int b   = rem / NPTS;

    const float4 q = g_sorted[dir][rem];
    const float4* __restrict__ cand = &g_sorted[dir ^ 1][b * NPTS];
    const int*    __restrict__ off  = g_off[dir ^ 1][b];

    float best = 3.4e38f;

    #define SCAN_BUCKET(bi) do {                                           \
        int s0 = off[bi], e0 = off[(bi) + 1];                              \
        for (int t = s0; t < e0; t++) {                                    \
            float4 c = cand[t];                                            \
            float dx = q.x - c.x, dy = q.y - c.y, dz = q.z - c.z;          \
            float d = fmaf(dx, dx, fmaf(dy, dy, dz * dz));                 \
            best = fminf(best, d);                                         \
        }                                                                  \
    } while (0)

    const int qb = bucket_of(q.x);
    SCAN_BUCKET(qb);

    int bl = qb, br = qb;
    while (true) {
        bool cl = (bl > 0);
        bool cr = (br < NB - 1);
        if (cl) {   // bucket bl-1: all points have x <= XMIN + bl*BH
            float d = q.x - (XMIN + (float)bl * BH);
            cl = (d * d < best);
        }
        if (cr) {   // bucket br+1: all points have x >= XMIN + (br+1)*BH
            float d = (XMIN + (float)(br + 1) * BH) - q.x;
            cr = (d * d < best);
        }
        if (!cl && !cr) break;
        if (cl) { bl--; SCAN_BUCKET(bl); }
        if (cr) { br++; SCAN_BUCKET(br); }
    }
    #undef SCAN_BUCKET

    g_min[dir][rem] = best;
}

__global__ void reduce_kernel(float* __restrict__ out) {
    __shared__ float ssum[32];
    const int tid = threadIdx.x;
    const float* vals = (const float*)g_min;

    float s = 0.0f;
    for (int i = tid; i < 2 * TOTAL; i += blockDim.x)
        s += vals[i];

    #pragma unroll
    for (int o = 16; o; o >>= 1) s += __shfl_down_sync(0xffffffffu, s, o);
    if ((tid & 31) == 0) ssum[tid >> 5] = s;
    __syncthreads();
    if (tid < 32) {
        s = (tid < (int)(blockDim.x >> 5)) ? ssum[tid] : 0.0f;
        #pragma unroll
        for (int o = 16; o; o >>= 1) s += __shfl_down_sync(0xffffffffu, s, o);
        if (tid == 0) out[0] = s / (float)(BATCH * NPTS);
    }
}

extern "C" void kernel_launch(void* const* d_in, const int* in_sizes, int n_in,
                              void* d_out, int out_size) {
    const float* p1 = (const float*)d_in[0];
    const float* p2 = (const float*)d_in[1];

    zero_kernel<<<(2 * BATCH * NB + 255) / 256, 256>>>();
    hist_kernel<<<(TOTAL + 255) / 256, 256>>>(p1, p2);
    prefix_kernel<<<2 * BATCH, NB>>>();
    scatter_kernel<<<(TOTAL + 255) / 256, 256>>>(p1, p2);
    nn_kernel<<<(2 * TOTAL + 255) / 256, 256>>>();
    reduce_kernel<<<1, 1024>>>((float*)d_out);
}